// round 3
// baseline (speedup 1.0000x reference)
#include <cuda_runtime.h>

#define NB 64
#define NM 1024
#define NK 16
#define NH 64
#define NN (NB*NM)

// ---------------- scratch (device globals; no allocations allowed) ----------
__device__ float g_h0[NN*NH];
__device__ float g_h1[NN*NH];
__device__ float g_sq[NN];
__device__ int   g_knn[NN*NK];

// ---------------- encoder: x[N,4] -> relu(relu(x@w1+b1)@w2+b2) -> g_h0, g_sq
__global__ __launch_bounds__(256) void k_encoder(
    const float* __restrict__ x,
    const float* __restrict__ w1, const float* __restrict__ b1,
    const float* __restrict__ w2, const float* __restrict__ b2)
{
    __shared__ float sw1[128], sb1[32], sw2[2048], sb2[64];
    int t = threadIdx.x;
    if (t < 128) sw1[t] = w1[t];
    if (t < 32)  sb1[t] = b1[t];
    if (t < 64)  sb2[t] = b2[t];
    for (int i = t; i < 2048; i += 256) sw2[i] = w2[i];
    __syncthreads();

    int node = blockIdx.x * 256 + t;
    float x0 = x[node*4+0], x1 = x[node*4+1], x2 = x[node*4+2], x3 = x[node*4+3];
    float hid[32];
    #pragma unroll
    for (int c = 0; c < 32; c++) {
        float a = sb1[c];
        a = fmaf(x0, sw1[c],      a);
        a = fmaf(x1, sw1[32+c],   a);
        a = fmaf(x2, sw1[64+c],   a);
        a = fmaf(x3, sw1[96+c],   a);
        hid[c] = fmaxf(a, 0.f);
    }
    float sq = 0.f;
    float* hrow = g_h0 + (size_t)node * NH;
    #pragma unroll 4
    for (int c4 = 0; c4 < 64; c4 += 4) {
        float a0 = sb2[c4], a1 = sb2[c4+1], a2 = sb2[c4+2], a3 = sb2[c4+3];
        #pragma unroll
        for (int k = 0; k < 32; k++) {
            float hv = hid[k];
            a0 = fmaf(hv, sw2[k*64+c4+0], a0);
            a1 = fmaf(hv, sw2[k*64+c4+1], a1);
            a2 = fmaf(hv, sw2[k*64+c4+2], a2);
            a3 = fmaf(hv, sw2[k*64+c4+3], a3);
        }
        a0 = fmaxf(a0,0.f); a1 = fmaxf(a1,0.f); a2 = fmaxf(a2,0.f); a3 = fmaxf(a3,0.f);
        *(float4*)(hrow + c4) = make_float4(a0,a1,a2,a3);
        sq = fmaf(a0,a0, fmaf(a1,a1, fmaf(a2,a2, fmaf(a3,a3, sq))));
    }
    g_sq[node] = sq;
}

// ---------------- kNN: per graph, top-16 smallest (sq_j - 2*dot), self excluded
// grid (8, 64): blockIdx.x = 128-row tile, blockIdx.y = graph. 128 threads.
__global__ __launch_bounds__(128) void k_knn(int src)
{
    const float* __restrict__ h = src ? g_h1 : g_h0;
    int b = blockIdx.y;
    int t = threadIdx.x;
    int myrow = blockIdx.x * 128 + t;          // local row in [0,1024)
    const float* hb = h + (size_t)b * NM * NH;

    __shared__ float4 hj[128*16];              // 32 KB j-tile
    __shared__ float  sqj[128];
    __shared__ float  topd[16*128];            // [slot][thread] — conflict-free
    __shared__ unsigned short topi[16*128];

    float4 hi[16];
    {
        const float4* r = (const float4*)(hb + (size_t)myrow * NH);
        #pragma unroll
        for (int f = 0; f < 16; f++) hi[f] = r[f];
    }
    #pragma unroll
    for (int s = 0; s < 16; s++) topd[s*128 + t] = __int_as_float(0x7f800000);
    float curmax = __int_as_float(0x7f800000);
    int maxpos = 0;

    for (int j0 = 0; j0 < NM; j0 += 128) {
        __syncthreads();
        {
            const float4* src4 = (const float4*)(hb + (size_t)j0 * NH);
            for (int i = t; i < 128*16; i += 128) hj[i] = src4[i];
            sqj[t] = g_sq[b*NM + j0 + t];
        }
        __syncthreads();
        for (int jj = 0; jj < 128; jj++) {
            float a0=0.f, a1=0.f, a2=0.f, a3=0.f;   // 4 chains for ILP
            const float4* hjr = &hj[jj*16];
            #pragma unroll
            for (int f = 0; f < 16; f++) {
                float4 bv = hjr[f];
                a0 = fmaf(hi[f].x, bv.x, a0);
                a1 = fmaf(hi[f].y, bv.y, a1);
                a2 = fmaf(hi[f].z, bv.z, a2);
                a3 = fmaf(hi[f].w, bv.w, a3);
            }
            float key = sqj[jj] - 2.f * ((a0+a1) + (a2+a3));
            int j = j0 + jj;
            if (key < curmax && j != myrow) {
                topd[maxpos*128 + t] = key;
                topi[maxpos*128 + t] = (unsigned short)j;
                curmax = -__int_as_float(0x7f800000);
                #pragma unroll
                for (int s = 0; s < 16; s++) {
                    float v = topd[s*128 + t];
                    if (v > curmax) { curmax = v; maxpos = s; }
                }
            }
        }
    }
    int* out = g_knn + (size_t)(b*NM + myrow) * NK;
    #pragma unroll
    for (int s = 0; s < 16; s++) out[s] = b*NM + (int)topi[s*128 + t];
}

// ---------------- EdgeConv MLP + max aggregation + sq epilogue
// 8 nodes (128 edges) per block, 256 threads, 4x8 register tiles.
// Dynamic smem layout (floats): w1s 8192 | w2s 4096 | DH 8320 | his 512 | b1 64 | b2 64 | jid 128(int)
#define EC_SMEM_BYTES ((21248 + 128) * 4)

__global__ __launch_bounds__(256, 2) void k_edgeconv(
    int src,
    const float* __restrict__ w1, const float* __restrict__ b1,
    const float* __restrict__ w2, const float* __restrict__ b2)
{
    extern __shared__ float sm[];
    float* w1s = sm;                 // [128][64]
    float* w2s = sm + 8192;          // [64][64]
    float* DH  = sm + 12288;         // Dsm_t[64][128] -> Hrow[128][65] -> P/V
    float* his = sm + 20608;         // [8][64]
    float* b1s = sm + 21120;
    float* b2s = sm + 21184;
    int*   jid = (int*)(sm + 21248); // [128]

    const float* hin  = src ? g_h1 : g_h0;
    float*       hout = src ? g_h0 : g_h1;

    int t = threadIdx.x;
    int node0 = blockIdx.x * 8;

    for (int i = t; i < 8192; i += 256) w1s[i] = w1[i];
    for (int i = t; i < 4096; i += 256) w2s[i] = w2[i];
    if (t < 64) { b1s[t] = b1[t]; b2s[t] = b2[t]; }
    if (t < 128) ((float4*)his)[t] = ((const float4*)(hin + (size_t)node0 * NH))[t];
    if (t >= 128) jid[t-128] = g_knn[node0*NK + (t-128)];
    __syncthreads();

    // stage D = x_j - x_i in [k][e] layout (64 x 128)
    if (t < 128) {
        int e = t, n = e >> 4;
        const float4* hj4 = (const float4*)(hin + (size_t)jid[e] * NH);
        const float4* hi4 = (const float4*)(his + n * NH);
        #pragma unroll
        for (int f = 0; f < 16; f++) {
            float4 a = hj4[f]; float4 c = hi4[f];
            DH[(4*f+0)*128 + e] = a.x - c.x;
            DH[(4*f+1)*128 + e] = a.y - c.y;
            DH[(4*f+2)*128 + e] = a.z - c.z;
            DH[(4*f+3)*128 + e] = a.w - c.w;
        }
    }
    __syncthreads();

    int cg = t & 7, eg = t >> 3;
    int n  = eg >> 2;                  // node local (one per warp)
    int e0 = eg << 2;                  // 4 edges per thread
    int cb = cg << 3;                  // 8 channels per thread

    // ---- layer 1, x_i half: identical across a node's edges -> compute once
    float accX[8];
    #pragma unroll
    for (int j = 0; j < 8; j++) accX[j] = b1s[cb + j];
    #pragma unroll 4
    for (int k = 0; k < 64; k++) {
        float a = his[n*64 + k];
        float4 wA = *(const float4*)&w1s[k*64 + cb];
        float4 wB = *(const float4*)&w1s[k*64 + cb + 4];
        accX[0]=fmaf(a,wA.x,accX[0]); accX[1]=fmaf(a,wA.y,accX[1]);
        accX[2]=fmaf(a,wA.z,accX[2]); accX[3]=fmaf(a,wA.w,accX[3]);
        accX[4]=fmaf(a,wB.x,accX[4]); accX[5]=fmaf(a,wB.y,accX[5]);
        accX[6]=fmaf(a,wB.z,accX[6]); accX[7]=fmaf(a,wB.w,accX[7]);
    }
    // ---- layer 1, (x_j - x_i) half: per-edge GEMM
    float acc[4][8];
    #pragma unroll
    for (int i = 0; i < 4; i++)
        #pragma unroll
        for (int j = 0; j < 8; j++) acc[i][j] = 0.f;
    #pragma unroll 2
    for (int k = 0; k < 64; k++) {
        float4 av = *(const float4*)&DH[k*128 + e0];
        float4 wA = *(const float4*)&w1s[(64+k)*64 + cb];
        float4 wB = *(const float4*)&w1s[(64+k)*64 + cb + 4];
        float aa[4] = {av.x, av.y, av.z, av.w};
        float ww[8] = {wA.x,wA.y,wA.z,wA.w, wB.x,wB.y,wB.z,wB.w};
        #pragma unroll
        for (int i = 0; i < 4; i++)
            #pragma unroll
            for (int j = 0; j < 8; j++)
                acc[i][j] = fmaf(aa[i], ww[j], acc[i][j]);
    }
    __syncthreads();   // everyone done reading Dsm region of DH
    #pragma unroll
    for (int i = 0; i < 4; i++)
        #pragma unroll
        for (int j = 0; j < 8; j++)
            DH[(e0+i)*65 + cb + j] = fmaxf(acc[i][j] + accX[j], 0.f);  // Hrow, LDE=65
    __syncthreads();

    // ---- layer 2
    float o[4][8];
    #pragma unroll
    for (int i = 0; i < 4; i++)
        #pragma unroll
        for (int j = 0; j < 8; j++) o[i][j] = b2s[cb + j];
    #pragma unroll 2
    for (int k = 0; k < 64; k++) {
        float aa[4];
        #pragma unroll
        for (int i = 0; i < 4; i++) aa[i] = DH[(e0+i)*65 + k];
        float4 wA = *(const float4*)&w2s[k*64 + cb];
        float4 wB = *(const float4*)&w2s[k*64 + cb + 4];
        float ww[8] = {wA.x,wA.y,wA.z,wA.w, wB.x,wB.y,wB.z,wB.w};
        #pragma unroll
        for (int i = 0; i < 4; i++)
            #pragma unroll
            for (int j = 0; j < 8; j++)
                o[i][j] = fmaf(aa[i], ww[j], o[i][j]);
    }
    // ---- max over this thread's 4 edges (same node)
    float m[8];
    #pragma unroll
    for (int j = 0; j < 8; j++)
        m[j] = fmaxf(fmaxf(o[0][j], o[1][j]), fmaxf(o[2][j], o[3][j]));
    __syncthreads();   // done reading Hrow
    #pragma unroll
    for (int j = 0; j < 8; j++) DH[eg*64 + cb + j] = m[j];   // P[32][64]
    __syncthreads();

    // combine 4 edge-groups per node; write hout; stash row for sq
    for (int s = t; s < 512; s += 256) {
        int nn = s >> 6, c = s & 63;
        float v = fmaxf(fmaxf(DH[(nn*4+0)*64 + c], DH[(nn*4+1)*64 + c]),
                        fmaxf(DH[(nn*4+2)*64 + c], DH[(nn*4+3)*64 + c]));
        DH[2048 + s] = v;
        hout[(size_t)(node0 + nn) * NH + c] = v;
    }
    __syncthreads();

    // squared norms for the next kNN: one warp per node
    {
        int w = t >> 5, lane = t & 31;
        float v0 = DH[2048 + w*64 + lane];
        float v1 = DH[2048 + w*64 + 32 + lane];
        float s2 = v0*v0 + v1*v1;
        #pragma unroll
        for (int off = 16; off > 0; off >>= 1)
            s2 += __shfl_down_sync(0xffffffffu, s2, off);
        if (lane == 0) g_sq[node0 + w] = s2;
    }
}

// ---------------- mean pool + output MLP -> d_out[64]
__global__ __launch_bounds__(256) void k_final(
    const float* __restrict__ w1, const float* __restrict__ b1,
    const float* __restrict__ w2, const float* __restrict__ b2,
    float* __restrict__ out)
{
    int b = blockIdx.x, t = threadIdx.x;
    const float* hb = g_h0 + (size_t)b * NM * NH;   // edgeconv2 wrote g_h0
    __shared__ float red[256];
    __shared__ float g[64];
    __shared__ float hid[32];

    int c = t & 63, r0 = t >> 6;
    float acc = 0.f;
    for (int m = r0; m < NM; m += 4) acc += hb[(size_t)m * NH + c];
    red[t] = acc;
    __syncthreads();
    if (t < 64)
        g[t] = (red[t] + red[t+64] + red[t+128] + red[t+192]) * (1.f/1024.f);
    __syncthreads();
    if (t < 32) {
        float a = b1[t];
        #pragma unroll 8
        for (int k = 0; k < 64; k++) a = fmaf(g[k], w1[k*32 + t], a);
        hid[t] = fmaxf(a, 0.f);
    }
    __syncthreads();
    if (t < 32) {
        float v = hid[t] * w2[t];
        #pragma unroll
        for (int off = 16; off > 0; off >>= 1)
            v += __shfl_down_sync(0xffffffffu, v, off);
        if (t == 0) out[b] = v + b2[0];
    }
}

// ---------------- launch ----------------------------------------------------
extern "C" void kernel_launch(void* const* d_in, const int* in_sizes, int n_in,
                              void* d_out, int out_size)
{
    const float* x      = (const float*)d_in[0];
    // d_in[1] = batch (int64) — equal-size graphs, unused
    const float* enc_w1 = (const float*)d_in[2];
    const float* enc_b1 = (const float*)d_in[3];
    const float* enc_w2 = (const float*)d_in[4];
    const float* enc_b2 = (const float*)d_in[5];
    const float* ec1_w1 = (const float*)d_in[6];
    const float* ec1_b1 = (const float*)d_in[7];
    const float* ec1_w2 = (const float*)d_in[8];
    const float* ec1_b2 = (const float*)d_in[9];
    const float* ec2_w1 = (const float*)d_in[10];
    const float* ec2_b1 = (const float*)d_in[11];
    const float* ec2_w2 = (const float*)d_in[12];
    const float* ec2_b2 = (const float*)d_in[13];
    const float* out_w1 = (const float*)d_in[14];
    const float* out_b1 = (const float*)d_in[15];
    const float* out_w2 = (const float*)d_in[16];
    const float* out_b2 = (const float*)d_in[17];
    float* out = (float*)d_out;

    cudaFuncSetAttribute(k_edgeconv, cudaFuncAttributeMaxDynamicSharedMemorySize,
                         EC_SMEM_BYTES);

    k_encoder<<<NN/256, 256>>>(x, enc_w1, enc_b1, enc_w2, enc_b2);
    k_knn<<<dim3(NM/128, NB), 128>>>(0);
    k_edgeconv<<<NN/8, 256, EC_SMEM_BYTES>>>(0, ec1_w1, ec1_b1, ec1_w2, ec1_b2);
    k_knn<<<dim3(NM/128, NB), 128>>>(1);
    k_edgeconv<<<NN/8, 256, EC_SMEM_BYTES>>>(1, ec2_w1, ec2_b1, ec2_w2, ec2_b2);
    k_final<<<NB, 256>>>(out_w1, out_b1, out_w2, out_b2, out);
}

// round 4
// speedup vs baseline: 1.1869x; 1.1869x over previous
#include <cuda_runtime.h>

#define NB 64
#define NM 1024
#define NK 16
#define NH 64
#define NN (NB*NM)

typedef unsigned long long ull;

__device__ __forceinline__ ull ffma2(ull a, ull b, ull c) {
    ull d;
    asm("fma.rn.f32x2 %0, %1, %2, %3;" : "=l"(d) : "l"(a), "l"(b), "l"(c));
    return d;
}
__device__ __forceinline__ ull fadd2(ull a, ull b) {
    ull d;
    asm("add.rn.f32x2 %0, %1, %2;" : "=l"(d) : "l"(a), "l"(b));
    return d;
}
__device__ __forceinline__ float lo32(ull v) { return __uint_as_float((unsigned)v); }
__device__ __forceinline__ float hi32(ull v) { return __uint_as_float((unsigned)(v >> 32)); }
__device__ __forceinline__ float sum2(ull v) { return lo32(v) + hi32(v); }

// ---------------- scratch (device globals; no allocations allowed) ----------
__device__ float g_h0[NN*NH];
__device__ float g_h1[NN*NH];
__device__ float g_sq[NN];
__device__ int   g_knn[NN*NK];

// ---------------- encoder: x[N,4] -> relu(relu(x@w1+b1)@w2+b2) -> g_h0, g_sq
__global__ __launch_bounds__(256) void k_encoder(
    const float* __restrict__ x,
    const float* __restrict__ w1, const float* __restrict__ b1,
    const float* __restrict__ w2, const float* __restrict__ b2)
{
    __shared__ float sw1[128], sb1[32], sw2[2048], sb2[64];
    int t = threadIdx.x;
    if (t < 128) sw1[t] = w1[t];
    if (t < 32)  sb1[t] = b1[t];
    if (t < 64)  sb2[t] = b2[t];
    for (int i = t; i < 2048; i += 256) sw2[i] = w2[i];
    __syncthreads();

    int node = blockIdx.x * 256 + t;
    float x0 = x[node*4+0], x1 = x[node*4+1], x2 = x[node*4+2], x3 = x[node*4+3];
    float hid[32];
    #pragma unroll
    for (int c = 0; c < 32; c++) {
        float a = sb1[c];
        a = fmaf(x0, sw1[c],      a);
        a = fmaf(x1, sw1[32+c],   a);
        a = fmaf(x2, sw1[64+c],   a);
        a = fmaf(x3, sw1[96+c],   a);
        hid[c] = fmaxf(a, 0.f);
    }
    float sq = 0.f;
    float* hrow = g_h0 + (size_t)node * NH;
    #pragma unroll 4
    for (int c4 = 0; c4 < 64; c4 += 4) {
        float a0 = sb2[c4], a1 = sb2[c4+1], a2 = sb2[c4+2], a3 = sb2[c4+3];
        #pragma unroll
        for (int k = 0; k < 32; k++) {
            float hv = hid[k];
            a0 = fmaf(hv, sw2[k*64+c4+0], a0);
            a1 = fmaf(hv, sw2[k*64+c4+1], a1);
            a2 = fmaf(hv, sw2[k*64+c4+2], a2);
            a3 = fmaf(hv, sw2[k*64+c4+3], a3);
        }
        a0 = fmaxf(a0,0.f); a1 = fmaxf(a1,0.f); a2 = fmaxf(a2,0.f); a3 = fmaxf(a3,0.f);
        *(float4*)(hrow + c4) = make_float4(a0,a1,a2,a3);
        sq = fmaf(a0,a0, fmaf(a1,a1, fmaf(a2,a2, fmaf(a3,a3, sq))));
    }
    g_sq[node] = sq;
}

// ---------------- kNN v2: TI=2 rows/thread, f32x2 packed dot products
// grid (4, 64): blockIdx.x = 256-row tile, blockIdx.y = graph. 128 threads.
// dyn smem: hj 32768 | sqj 512 | topd 16384 | topi 8192  = 57856 B
#define KNN_SMEM_BYTES 57856

__global__ __launch_bounds__(128, 3) void k_knn(int src)
{
    extern __shared__ char ksm[];
    ull*   hj   = (ull*)ksm;                         // [128 rows][32 ull]
    float* sqj  = (float*)(ksm + 32768);             // [128]
    float* topd = (float*)(ksm + 33280);             // [2][16][128]
    unsigned short* topi = (unsigned short*)(ksm + 49664); // [2][16][128]

    const float* __restrict__ h = src ? g_h1 : g_h0;
    int b = blockIdx.y;
    int t = threadIdx.x;
    int rA = blockIdx.x * 256 + t;      // local rows in [0,1024)
    int rB = rA + 128;
    const float* hb = h + (size_t)b * NM * NH;

    ull hiA[32], hiB[32];
    {
        const ull* ra = (const ull*)(hb + (size_t)rA * NH);
        const ull* rb = (const ull*)(hb + (size_t)rB * NH);
        #pragma unroll
        for (int f = 0; f < 32; f++) { hiA[f] = ra[f]; hiB[f] = rb[f]; }
    }
    #pragma unroll
    for (int s = 0; s < 16; s++) {
        topd[s*128 + t]       = __int_as_float(0x7f800000);
        topd[(16+s)*128 + t]  = __int_as_float(0x7f800000);
    }
    float cmA = __int_as_float(0x7f800000); int mpA = 0;
    float cmB = __int_as_float(0x7f800000); int mpB = 0;

    for (int j0 = 0; j0 < NM; j0 += 128) {
        __syncthreads();
        {
            const ulonglong2* s4 = (const ulonglong2*)(hb + (size_t)j0 * NH);
            ulonglong2* d4 = (ulonglong2*)hj;
            for (int i = t; i < 128*16; i += 128) d4[i] = s4[i];
            sqj[t] = g_sq[b*NM + j0 + t];
        }
        __syncthreads();
        for (int jj = 0; jj < 128; jj++) {
            const ulonglong2* hr2 = (const ulonglong2*)&hj[jj*32];
            ull aA[4] = {0,0,0,0}, aB[4] = {0,0,0,0};
            #pragma unroll
            for (int f2 = 0; f2 < 16; f2++) {
                ulonglong2 v = hr2[f2];
                aA[(2*f2)   & 3] = ffma2(hiA[2*f2],   v.x, aA[(2*f2)   & 3]);
                aA[(2*f2+1) & 3] = ffma2(hiA[2*f2+1], v.y, aA[(2*f2+1) & 3]);
                aB[(2*f2)   & 3] = ffma2(hiB[2*f2],   v.x, aB[(2*f2)   & 3]);
                aB[(2*f2+1) & 3] = ffma2(hiB[2*f2+1], v.y, aB[(2*f2+1) & 3]);
            }
            float sj = sqj[jj];
            int j = j0 + jj;
            float dA = sum2(fadd2(fadd2(aA[0], aA[1]), fadd2(aA[2], aA[3])));
            float dB = sum2(fadd2(fadd2(aB[0], aB[1]), fadd2(aB[2], aB[3])));
            float keyA = sj - 2.f * dA;
            float keyB = sj - 2.f * dB;
            if (keyA < cmA && j != rA) {
                topd[mpA*128 + t] = keyA;
                topi[mpA*128 + t] = (unsigned short)j;
                cmA = -__int_as_float(0x7f800000);
                #pragma unroll
                for (int s = 0; s < 16; s++) {
                    float v = topd[s*128 + t];
                    if (v > cmA) { cmA = v; mpA = s; }
                }
            }
            if (keyB < cmB && j != rB) {
                topd[(16+mpB)*128 + t] = keyB;
                topi[(16+mpB)*128 + t] = (unsigned short)j;
                cmB = -__int_as_float(0x7f800000);
                #pragma unroll
                for (int s = 0; s < 16; s++) {
                    float v = topd[(16+s)*128 + t];
                    if (v > cmB) { cmB = v; mpB = s; }
                }
            }
        }
    }
    int* outA = g_knn + (size_t)(b*NM + rA) * NK;
    int* outB = g_knn + (size_t)(b*NM + rB) * NK;
    #pragma unroll
    for (int s = 0; s < 16; s++) {
        outA[s] = b*NM + (int)topi[s*128 + t];
        outB[s] = b*NM + (int)topi[(16+s)*128 + t];
    }
}

// ---------------- EdgeConv v2: f32x2 packed along the reduction dim
// 8 nodes (128 edges) per block, 256 threads, 4 edges x 8 channels per thread.
// k-major XOR-swizzled smem layouts; x_i@W1 half folded into per-node bias.
// smem floats: w1x 4096 | w1Td 4096 | w2T 4096 | DH/Hrow 8192 | his 512 |
//              bnode 512 | b2s 64 | jid 128(int)
#define EC_SMEM_BYTES ((21568 + 128) * 4)

__global__ __launch_bounds__(256, 2) void k_edgeconv(
    int src,
    const float* __restrict__ w1, const float* __restrict__ b1,
    const float* __restrict__ w2, const float* __restrict__ b2)
{
    extern __shared__ float sm[];
    float* w1x   = sm;                 // [k][c], k<64 (untransposed)
    float* w1Td  = sm + 4096;          // [cout][kin] swizzled
    float* w2T   = sm + 8192;          // [cout][cin] swizzled
    float* DH    = sm + 12288;         // [e][k] swizzled; reused as Hrow
    float* his   = sm + 20480;         // [8][64]
    float* bnode = sm + 20992;         // [8][64]
    float* b2s   = sm + 21504;
    int*   jid   = (int*)(sm + 21568);

    const float* hin  = src ? g_h1 : g_h0;
    float*       hout = src ? g_h0 : g_h1;

    int t = threadIdx.x;
    int node0 = blockIdx.x * 8;

    // -------- phase 0: stage weights (transposed+swizzled), his, jid
    for (int i = t; i < 4096; i += 256) w1x[i] = w1[i];
    for (int i = t; i < 4096; i += 256) {
        int c = i & 63, k = i >> 6;
        w1Td[c*64 + ((((k>>2) ^ (c>>3)) & 15) << 2) + (k & 3)] = w1[(64+k)*64 + c];
    }
    for (int i = t; i < 4096; i += 256) {
        int c = i & 63, k = i >> 6;
        w2T[c*64 + ((((k>>2) ^ (c>>3)) & 15) << 2) + (k & 3)] = w2[k*64 + c];
    }
    if (t < 64) b2s[t] = b2[t];
    if (t < 128) ((float4*)his)[t] = ((const float4*)(hin + (size_t)node0 * NH))[t];
    if (t >= 128) jid[t-128] = g_knn[node0*NK + (t-128)];
    __syncthreads();

    // -------- phase 1: DH = (x_j - x_i) staged k-major; bnode = x_i@W1x + b1
    if (t >= 128) {
        int e = t - 128;
        int n = e >> 4;
        const float4* hj4 = (const float4*)(hin + (size_t)jid[e] * NH);
        const float4* hi4 = (const float4*)(his + n * NH);
        int ebase = e * 64, esw = (e >> 2) & 3;
        #pragma unroll
        for (int f = 0; f < 16; f++) {
            float4 a = hj4[f]; float4 c = hi4[f];
            *(float4*)&DH[ebase + ((f ^ esw) << 2)] =
                make_float4(a.x - c.x, a.y - c.y, a.z - c.z, a.w - c.w);
        }
    } else {
        int n = t >> 4, c0 = (t & 15) << 2;
        float a0 = b1[c0], a1 = b1[c0+1], a2 = b1[c0+2], a3 = b1[c0+3];
        #pragma unroll 4
        for (int k4 = 0; k4 < 16; k4++) {
            float4 av = *(const float4*)&his[n*64 + 4*k4];
            float aa[4] = {av.x, av.y, av.z, av.w};
            #pragma unroll
            for (int kk = 0; kk < 4; kk++) {
                float4 w = *(const float4*)&w1x[(4*k4+kk)*64 + c0];
                a0 = fmaf(aa[kk], w.x, a0);
                a1 = fmaf(aa[kk], w.y, a1);
                a2 = fmaf(aa[kk], w.z, a2);
                a3 = fmaf(aa[kk], w.w, a3);
            }
        }
        *(float4*)&bnode[n*64 + c0] = make_float4(a0, a1, a2, a3);
    }
    __syncthreads();

    int cg = t & 7, eg = t >> 3;
    int e0 = eg << 2, cb = cg << 3;
    int n  = eg >> 2;
    int esw = eg & 3;

    // -------- layer 1 (diff half), packed along kin
    ull acc[4][8];
    #pragma unroll
    for (int i = 0; i < 4; i++)
        #pragma unroll
        for (int j = 0; j < 8; j++) acc[i][j] = 0ull;

    #pragma unroll 2
    for (int k4 = 0; k4 < 16; k4++) {
        int sa = (k4 ^ esw) << 2;
        ulonglong2 av[4];
        #pragma unroll
        for (int i = 0; i < 4; i++)
            av[i] = *(const ulonglong2*)&DH[(e0+i)*64 + sa];
        int sw = (k4 ^ cg) << 2;
        #pragma unroll
        for (int j = 0; j < 8; j++) {
            ulonglong2 wv = *(const ulonglong2*)&w1Td[(cb+j)*64 + sw];
            #pragma unroll
            for (int i = 0; i < 4; i++) {
                acc[i][j] = ffma2(av[i].x, wv.x, acc[i][j]);
                acc[i][j] = ffma2(av[i].y, wv.y, acc[i][j]);
            }
        }
    }
    __syncthreads();   // all DH reads complete

    // relu(bnode + diff) -> Hrow (aliases DH), k-major swizzled
    {
        float4 bn0 = *(const float4*)&bnode[n*64 + cb];
        float4 bn1 = *(const float4*)&bnode[n*64 + cb + 4];
        float bb[8] = {bn0.x,bn0.y,bn0.z,bn0.w, bn1.x,bn1.y,bn1.z,bn1.w};
        int s0 = ((cb>>2) ^ esw) << 2;
        int s1 = (((cb>>2)+1) ^ esw) << 2;
        #pragma unroll
        for (int i = 0; i < 4; i++) {
            int e = e0 + i;
            float h0 = fmaxf(bb[0] + sum2(acc[i][0]), 0.f);
            float h1 = fmaxf(bb[1] + sum2(acc[i][1]), 0.f);
            float h2 = fmaxf(bb[2] + sum2(acc[i][2]), 0.f);
            float h3 = fmaxf(bb[3] + sum2(acc[i][3]), 0.f);
            float h4 = fmaxf(bb[4] + sum2(acc[i][4]), 0.f);
            float h5 = fmaxf(bb[5] + sum2(acc[i][5]), 0.f);
            float h6 = fmaxf(bb[6] + sum2(acc[i][6]), 0.f);
            float h7 = fmaxf(bb[7] + sum2(acc[i][7]), 0.f);
            *(float4*)&DH[e*64 + s0] = make_float4(h0, h1, h2, h3);
            *(float4*)&DH[e*64 + s1] = make_float4(h4, h5, h6, h7);
        }
    }
    __syncthreads();

    // -------- layer 2, packed along cin
    ull acc2[4][8];
    #pragma unroll
    for (int i = 0; i < 4; i++)
        #pragma unroll
        for (int j = 0; j < 8; j++) acc2[i][j] = 0ull;

    #pragma unroll 2
    for (int k4 = 0; k4 < 16; k4++) {
        int sa = (k4 ^ esw) << 2;
        ulonglong2 av[4];
        #pragma unroll
        for (int i = 0; i < 4; i++)
            av[i] = *(const ulonglong2*)&DH[(e0+i)*64 + sa];
        int sw = (k4 ^ cg) << 2;
        #pragma unroll
        for (int j = 0; j < 8; j++) {
            ulonglong2 wv = *(const ulonglong2*)&w2T[(cb+j)*64 + sw];
            #pragma unroll
            for (int i = 0; i < 4; i++) {
                acc2[i][j] = ffma2(av[i].x, wv.x, acc2[i][j]);
                acc2[i][j] = ffma2(av[i].y, wv.y, acc2[i][j]);
            }
        }
    }

    // -------- epilogue: +b2, max over 4 edges, warp-shfl max over edge groups
    float m[8];
    #pragma unroll
    for (int j = 0; j < 8; j++) {
        float bj = b2s[cb + j];
        float v0 = bj + sum2(acc2[0][j]);
        float v1 = bj + sum2(acc2[1][j]);
        float v2 = bj + sum2(acc2[2][j]);
        float v3 = bj + sum2(acc2[3][j]);
        m[j] = fmaxf(fmaxf(v0, v1), fmaxf(v2, v3));
    }
    #pragma unroll
    for (int j = 0; j < 8; j++) {
        m[j] = fmaxf(m[j], __shfl_xor_sync(0xffffffffu, m[j], 8));
        m[j] = fmaxf(m[j], __shfl_xor_sync(0xffffffffu, m[j], 16));
    }
    if (esw == 0) {
        float* orow = hout + (size_t)(node0 + n) * NH + cb;
        *(float4*)orow     = make_float4(m[0], m[1], m[2], m[3]);
        *(float4*)(orow+4) = make_float4(m[4], m[5], m[6], m[7]);
    }
    // squared norms for the next kNN
    float s2 = 0.f;
    #pragma unroll
    for (int j = 0; j < 8; j++) s2 = fmaf(m[j], m[j], s2);
    s2 += __shfl_xor_sync(0xffffffffu, s2, 1);
    s2 += __shfl_xor_sync(0xffffffffu, s2, 2);
    s2 += __shfl_xor_sync(0xffffffffu, s2, 4);
    if ((t & 31) == 0) g_sq[node0 + n] = s2;
}

// ---------------- mean pool + output MLP -> d_out[64]
__global__ __launch_bounds__(256) void k_final(
    const float* __restrict__ w1, const float* __restrict__ b1,
    const float* __restrict__ w2, const float* __restrict__ b2,
    float* __restrict__ out)
{
    int b = blockIdx.x, t = threadIdx.x;
    const float* hb = g_h0 + (size_t)b * NM * NH;   // edgeconv2 wrote g_h0
    __shared__ float red[256];
    __shared__ float g[64];
    __shared__ float hid[32];

    int c = t & 63, r0 = t >> 6;
    float acc = 0.f;
    for (int m = r0; m < NM; m += 4) acc += hb[(size_t)m * NH + c];
    red[t] = acc;
    __syncthreads();
    if (t < 64)
        g[t] = (red[t] + red[t+64] + red[t+128] + red[t+192]) * (1.f/1024.f);
    __syncthreads();
    if (t < 32) {
        float a = b1[t];
        #pragma unroll 8
        for (int k = 0; k < 64; k++) a = fmaf(g[k], w1[k*32 + t], a);
        hid[t] = fmaxf(a, 0.f);
    }
    __syncthreads();
    if (t < 32) {
        float v = hid[t] * w2[t];
        #pragma unroll
        for (int off = 16; off > 0; off >>= 1)
            v += __shfl_down_sync(0xffffffffu, v, off);
        if (t == 0) out[b] = v + b2[0];
    }
}

// ---------------- launch ----------------------------------------------------
extern "C" void kernel_launch(void* const* d_in, const int* in_sizes, int n_in,
                              void* d_out, int out_size)
{
    const float* x      = (const float*)d_in[0];
    // d_in[1] = batch (int64) — equal-size graphs, unused
    const float* enc_w1 = (const float*)d_in[2];
    const float* enc_b1 = (const float*)d_in[3];
    const float* enc_w2 = (const float*)d_in[4];
    const float* enc_b2 = (const float*)d_in[5];
    const float* ec1_w1 = (const float*)d_in[6];
    const float* ec1_b1 = (const float*)d_in[7];
    const float* ec1_w2 = (const float*)d_in[8];
    const float* ec1_b2 = (const float*)d_in[9];
    const float* ec2_w1 = (const float*)d_in[10];
    const float* ec2_b1 = (const float*)d_in[11];
    const float* ec2_w2 = (const float*)d_in[12];
    const float* ec2_b2 = (const float*)d_in[13];
    const float* out_w1 = (const float*)d_in[14];
    const float* out_b1 = (const float*)d_in[15];
    const float* out_w2 = (const float*)d_in[16];
    const float* out_b2 = (const float*)d_in[17];
    float* out = (float*)d_out;

    cudaFuncSetAttribute(k_edgeconv, cudaFuncAttributeMaxDynamicSharedMemorySize,
                         EC_SMEM_BYTES);
    cudaFuncSetAttribute(k_knn, cudaFuncAttributeMaxDynamicSharedMemorySize,
                         KNN_SMEM_BYTES);

    k_encoder<<<NN/256, 256>>>(x, enc_w1, enc_b1, enc_w2, enc_b2);
    k_knn<<<dim3(NM/256, NB), 128, KNN_SMEM_BYTES>>>(0);
    k_edgeconv<<<NN/8, 256, EC_SMEM_BYTES>>>(0, ec1_w1, ec1_b1, ec1_w2, ec1_b2);
    k_knn<<<dim3(NM/256, NB), 128, KNN_SMEM_BYTES>>>(1);
    k_edgeconv<<<NN/8, 256, EC_SMEM_BYTES>>>(1, ec2_w1, ec2_b1, ec2_w2, ec2_b2);
    k_final<<<NB, 256>>>(out_w1, out_b1, out_w2, out_b2, out);
}

// round 5
// speedup vs baseline: 1.3126x; 1.1059x over previous
#include <cuda_runtime.h>

#define NB 64
#define NM 1024
#define NK 16
#define NH 64
#define NN (NB*NM)
#define INF __int_as_float(0x7f800000)

typedef unsigned long long ull;

__device__ __forceinline__ ull ffma2(ull a, ull b, ull c) {
    ull d;
    asm("fma.rn.f32x2 %0, %1, %2, %3;" : "=l"(d) : "l"(a), "l"(b), "l"(c));
    return d;
}
__device__ __forceinline__ ull fadd2(ull a, ull b) {
    ull d;
    asm("add.rn.f32x2 %0, %1, %2;" : "=l"(d) : "l"(a), "l"(b));
    return d;
}
__device__ __forceinline__ float lo32(ull v) { return __uint_as_float((unsigned)v); }
__device__ __forceinline__ float hi32(ull v) { return __uint_as_float((unsigned)(v >> 32)); }
__device__ __forceinline__ float sum2(ull v) { return lo32(v) + hi32(v); }

// ---------------- scratch (device globals; no allocations allowed) ----------
__device__ float g_h0[NN*NH];
__device__ float g_h1[NN*NH];
__device__ float g_sq[NN];
__device__ int   g_knn[NN*NK];

// ---------------- encoder: x[N,4] -> relu(relu(x@w1+b1)@w2+b2) -> g_h0, g_sq
__global__ __launch_bounds__(256) void k_encoder(
    const float* __restrict__ x,
    const float* __restrict__ w1, const float* __restrict__ b1,
    const float* __restrict__ w2, const float* __restrict__ b2)
{
    __shared__ float sw1[128], sb1[32], sw2[2048], sb2[64];
    int t = threadIdx.x;
    if (t < 128) sw1[t] = w1[t];
    if (t < 32)  sb1[t] = b1[t];
    if (t < 64)  sb2[t] = b2[t];
    for (int i = t; i < 2048; i += 256) sw2[i] = w2[i];
    __syncthreads();

    int node = blockIdx.x * 256 + t;
    float x0 = x[node*4+0], x1 = x[node*4+1], x2 = x[node*4+2], x3 = x[node*4+3];
    float hid[32];
    #pragma unroll
    for (int c = 0; c < 32; c++) {
        float a = sb1[c];
        a = fmaf(x0, sw1[c],      a);
        a = fmaf(x1, sw1[32+c],   a);
        a = fmaf(x2, sw1[64+c],   a);
        a = fmaf(x3, sw1[96+c],   a);
        hid[c] = fmaxf(a, 0.f);
    }
    float sq = 0.f;
    float* hrow = g_h0 + (size_t)node * NH;
    #pragma unroll 4
    for (int c4 = 0; c4 < 64; c4 += 4) {
        float a0 = sb2[c4], a1 = sb2[c4+1], a2 = sb2[c4+2], a3 = sb2[c4+3];
        #pragma unroll
        for (int k = 0; k < 32; k++) {
            float hv = hid[k];
            a0 = fmaf(hv, sw2[k*64+c4+0], a0);
            a1 = fmaf(hv, sw2[k*64+c4+1], a1);
            a2 = fmaf(hv, sw2[k*64+c4+2], a2);
            a3 = fmaf(hv, sw2[k*64+c4+3], a3);
        }
        a0 = fmaxf(a0,0.f); a1 = fmaxf(a1,0.f); a2 = fmaxf(a2,0.f); a3 = fmaxf(a3,0.f);
        *(float4*)(hrow + c4) = make_float4(a0,a1,a2,a3);
        sq = fmaf(a0,a0, fmaf(a1,a1, fmaf(a2,a2, fmaf(a3,a3, sq))));
    }
    g_sq[node] = sq;
}

// ---------------- kNN v3: TI=2 via channel-split lane pairs, f32x2 dots
// grid (8, 64) = 512 blocks, 128 threads. Lane l and l^16 share 2 rows:
// l<16 holds ch[0:32), l>=16 holds ch[32:64); shfl_xor(16) merges partials.
// dyn smem: hj 32768 | sqj 512 | topd 8192 | topi 4096 = 45568 B
#define KNN_SMEM_BYTES 45568

__global__ __launch_bounds__(128, 4) void k_knn(int src)
{
    extern __shared__ char ksm[];
    ulonglong2* hj = (ulonglong2*)ksm;                      // [128 rows][16]
    float* sqj  = (float*)(ksm + 32768);                    // [128]
    float* topd = (float*)(ksm + 33280);                    // [16][128]
    unsigned short* topi = (unsigned short*)(ksm + 41472);  // [16][128]

    const float* __restrict__ h = src ? g_h1 : g_h0;
    const int b = blockIdx.y;
    const int t = threadIdx.x;
    const int lane = t & 31, w = t >> 5;
    const int half = lane >> 4;
    const int p = w * 16 + (lane & 15);
    const int rl = 2 * p + half;               // this thread's own local row
    const int base = blockIdx.x * 128;
    const int row_own = base + rl;
    const float* hb = h + (size_t)b * NM * NH;

    // register i-data: rows (base+2p, base+2p+1), this thread's channel half
    ulonglong2 hiA[8], hiB[8];
    {
        const ulonglong2* ra = (const ulonglong2*)(hb + (size_t)(base + 2*p) * NH) + half*8;
        const ulonglong2* rb = (const ulonglong2*)(hb + (size_t)(base + 2*p + 1) * NH) + half*8;
        #pragma unroll
        for (int c = 0; c < 8; c++) { hiA[c] = ra[c]; hiB[c] = rb[c]; }
    }
    #pragma unroll
    for (int s = 0; s < 16; s++) topd[s*128 + rl] = INF;
    float cm = INF; int mp = 0;

    for (int j0 = 0; j0 < NM; j0 += 128) {
        __syncthreads();
        {
            const ulonglong2* s4 = (const ulonglong2*)(hb + (size_t)j0 * NH);
            #pragma unroll
            for (int i = 0; i < 16; i++) hj[t + i*128] = s4[t + i*128];
            sqj[t] = g_sq[b*NM + j0 + t];
        }
        __syncthreads();
        #pragma unroll 2
        for (int jj = 0; jj < 128; jj++) {
            const ulonglong2* hr = &hj[jj*16 + half*8];
            ull a0=0, a1=0, b0=0, b1=0;
            #pragma unroll
            for (int s = 0; s < 8; s++) {
                int c = s ^ (half << 2);       // phase offset -> bank-disjoint halves
                ulonglong2 v = hr[c];
                a0 = ffma2(hiA[c].x, v.x, a0);
                a1 = ffma2(hiA[c].y, v.y, a1);
                b0 = ffma2(hiB[c].x, v.x, b0);
                b1 = ffma2(hiB[c].y, v.y, b1);
            }
            float pA = sum2(fadd2(a0, a1));
            float pB = sum2(fadd2(b0, b1));
            float qA = __shfl_xor_sync(0xffffffffu, pA, 16);
            float qB = __shfl_xor_sync(0xffffffffu, pB, 16);
            float dot = half ? (pB + qB) : (pA + qA);
            int j = j0 + jj;
            float key = fmaf(-2.f, dot, sqj[jj]);
            if (key < cm && j != row_own) {
                topd[mp*128 + rl] = key;
                topi[mp*128 + rl] = (unsigned short)j;
                cm = -INF;
                #pragma unroll
                for (int s = 0; s < 16; s++) {
                    float v = topd[s*128 + rl];
                    if (v > cm) { cm = v; mp = s; }
                }
            }
        }
    }
    int* out = g_knn + (size_t)(b*NM + row_own) * NK;
    #pragma unroll
    for (int s = 0; s < 16; s++) out[s] = b*NM + (int)topi[s*128 + rl];
}

// ---------------- EdgeConv v3: persistent blocks, weights staged once
// 8 nodes (128 edges) per tile, 256 threads, 4 edges x 8 channels per thread.
// smem floats: w1x 4096 | w1Td 4096 | w2T 4096 | DH 8192 | his 512 |
//              bnode 512 | b1s 64 | b2s 64 | jid 128(int)  = 87040 B
#define EC_SMEM_BYTES (21760 * 4)
#define EC_GRID 296
#define NTILES (NN/8)

__global__ __launch_bounds__(256, 2) void k_edgeconv(
    int src,
    const float* __restrict__ w1, const float* __restrict__ b1,
    const float* __restrict__ w2, const float* __restrict__ b2)
{
    extern __shared__ float sm[];
    float* w1x   = sm;                 // [k][c], k<64 (untransposed)
    float* w1Td  = sm + 4096;          // [cout][kin] swizzled
    float* w2T   = sm + 8192;          // [cout][cin] swizzled
    float* DH    = sm + 12288;         // [e][k] swizzled; reused as Hrow
    float* his   = sm + 20480;         // [8][64]
    float* bnode = sm + 20992;         // [8][64]
    float* b1s   = sm + 21504;
    float* b2s   = sm + 21568;
    int*   jid   = (int*)(sm + 21632);

    const float* hin  = src ? g_h1 : g_h0;
    float*       hout = src ? g_h0 : g_h1;

    const int t = threadIdx.x;

    // -------- stage weights ONCE (transposed + XOR-swizzled)
    for (int i = t; i < 4096; i += 256) w1x[i] = w1[i];
    for (int i = t; i < 4096; i += 256) {
        int c = i & 63, k = i >> 6;
        w1Td[c*64 + ((((k>>2) ^ (c>>3)) & 15) << 2) + (k & 3)] = w1[(64+k)*64 + c];
    }
    for (int i = t; i < 4096; i += 256) {
        int c = i & 63, k = i >> 6;
        w2T[c*64 + ((((k>>2) ^ (c>>3)) & 15) << 2) + (k & 3)] = w2[k*64 + c];
    }
    if (t < 64) { b1s[t] = b1[t]; b2s[t] = b2[t]; }

    const int cg = t & 7, eg = t >> 3;
    const int e0 = eg << 2, cb = cg << 3;
    const int n  = eg >> 2;
    const int esw = eg & 3;

    for (int tile = blockIdx.x; tile < NTILES; tile += EC_GRID) {
        int node0 = tile * 8;
        __syncthreads();   // previous tile fully done with his/jid/DH

        if (t < 128) ((float4*)his)[t] = ((const float4*)(hin + (size_t)node0 * NH))[t];
        else         jid[t-128] = g_knn[node0*NK + (t-128)];
        __syncthreads();

        // -------- phase 1: DH = (x_j - x_i) k-major swizzled; bnode = x_i@W1x + b1
        if (t >= 128) {
            int e = t - 128;
            int nn = e >> 4;
            const float4* hj4 = (const float4*)(hin + (size_t)jid[e] * NH);
            const float4* hi4 = (const float4*)(his + nn * NH);
            int ebase = e * 64, es = (e >> 2) & 3;
            #pragma unroll
            for (int f = 0; f < 16; f++) {
                float4 a = hj4[f]; float4 c = hi4[f];
                *(float4*)&DH[ebase + ((f ^ es) << 2)] =
                    make_float4(a.x - c.x, a.y - c.y, a.z - c.z, a.w - c.w);
            }
        } else {
            int nn = t >> 4, c0 = (t & 15) << 2;
            float a0 = b1s[c0], a1 = b1s[c0+1], a2 = b1s[c0+2], a3 = b1s[c0+3];
            #pragma unroll 4
            for (int k4 = 0; k4 < 16; k4++) {
                float4 av = *(const float4*)&his[nn*64 + 4*k4];
                float aa[4] = {av.x, av.y, av.z, av.w};
                #pragma unroll
                for (int kk = 0; kk < 4; kk++) {
                    float4 wv = *(const float4*)&w1x[(4*k4+kk)*64 + c0];
                    a0 = fmaf(aa[kk], wv.x, a0);
                    a1 = fmaf(aa[kk], wv.y, a1);
                    a2 = fmaf(aa[kk], wv.z, a2);
                    a3 = fmaf(aa[kk], wv.w, a3);
                }
            }
            *(float4*)&bnode[nn*64 + c0] = make_float4(a0, a1, a2, a3);
        }
        __syncthreads();

        // -------- layer 1 (diff half), f32x2 packed along kin
        ull acc[4][8];
        #pragma unroll
        for (int i = 0; i < 4; i++)
            #pragma unroll
            for (int j = 0; j < 8; j++) acc[i][j] = 0ull;

        #pragma unroll 2
        for (int k4 = 0; k4 < 16; k4++) {
            int sa = (k4 ^ esw) << 2;
            ulonglong2 av[4];
            #pragma unroll
            for (int i = 0; i < 4; i++)
                av[i] = *(const ulonglong2*)&DH[(e0+i)*64 + sa];
            int sw = (k4 ^ cg) << 2;
            #pragma unroll
            for (int j = 0; j < 8; j++) {
                ulonglong2 wv = *(const ulonglong2*)&w1Td[(cb+j)*64 + sw];
                #pragma unroll
                for (int i = 0; i < 4; i++) {
                    acc[i][j] = ffma2(av[i].x, wv.x, acc[i][j]);
                    acc[i][j] = ffma2(av[i].y, wv.y, acc[i][j]);
                }
            }
        }
        __syncthreads();   // all DH reads complete

        // relu(bnode + diff) -> Hrow (aliases DH), k-major swizzled
        {
            float4 bn0 = *(const float4*)&bnode[n*64 + cb];
            float4 bn1 = *(const float4*)&bnode[n*64 + cb + 4];
            float bb[8] = {bn0.x,bn0.y,bn0.z,bn0.w, bn1.x,bn1.y,bn1.z,bn1.w};
            int s0 = ((cb>>2) ^ esw) << 2;
            int s1 = (((cb>>2)+1) ^ esw) << 2;
            #pragma unroll
            for (int i = 0; i < 4; i++) {
                int e = e0 + i;
                float h0 = fmaxf(bb[0] + sum2(acc[i][0]), 0.f);
                float h1 = fmaxf(bb[1] + sum2(acc[i][1]), 0.f);
                float h2 = fmaxf(bb[2] + sum2(acc[i][2]), 0.f);
                float h3 = fmaxf(bb[3] + sum2(acc[i][3]), 0.f);
                float h4 = fmaxf(bb[4] + sum2(acc[i][4]), 0.f);
                float h5 = fmaxf(bb[5] + sum2(acc[i][5]), 0.f);
                float h6 = fmaxf(bb[6] + sum2(acc[i][6]), 0.f);
                float h7 = fmaxf(bb[7] + sum2(acc[i][7]), 0.f);
                *(float4*)&DH[e*64 + s0] = make_float4(h0, h1, h2, h3);
                *(float4*)&DH[e*64 + s1] = make_float4(h4, h5, h6, h7);
            }
        }
        __syncthreads();

        // -------- layer 2, f32x2 packed along cin
        ull acc2[4][8];
        #pragma unroll
        for (int i = 0; i < 4; i++)
            #pragma unroll
            for (int j = 0; j < 8; j++) acc2[i][j] = 0ull;

        #pragma unroll 2
        for (int k4 = 0; k4 < 16; k4++) {
            int sa = (k4 ^ esw) << 2;
            ulonglong2 av[4];
            #pragma unroll
            for (int i = 0; i < 4; i++)
                av[i] = *(const ulonglong2*)&DH[(e0+i)*64 + sa];
            int sw = (k4 ^ cg) << 2;
            #pragma unroll
            for (int j = 0; j < 8; j++) {
                ulonglong2 wv = *(const ulonglong2*)&w2T[(cb+j)*64 + sw];
                #pragma unroll
                for (int i = 0; i < 4; i++) {
                    acc2[i][j] = ffma2(av[i].x, wv.x, acc2[i][j]);
                    acc2[i][j] = ffma2(av[i].y, wv.y, acc2[i][j]);
                }
            }
        }

        // -------- epilogue: +b2, max over 4 edges, shfl-max over edge groups
        float m[8];
        #pragma unroll
        for (int j = 0; j < 8; j++) {
            float bj = b2s[cb + j];
            float v0 = bj + sum2(acc2[0][j]);
            float v1 = bj + sum2(acc2[1][j]);
            float v2 = bj + sum2(acc2[2][j]);
            float v3 = bj + sum2(acc2[3][j]);
            m[j] = fmaxf(fmaxf(v0, v1), fmaxf(v2, v3));
        }
        #pragma unroll
        for (int j = 0; j < 8; j++) {
            m[j] = fmaxf(m[j], __shfl_xor_sync(0xffffffffu, m[j], 8));
            m[j] = fmaxf(m[j], __shfl_xor_sync(0xffffffffu, m[j], 16));
        }
        if (esw == 0) {
            float* orow = hout + (size_t)(node0 + n) * NH + cb;
            *(float4*)orow     = make_float4(m[0], m[1], m[2], m[3]);
            *(float4*)(orow+4) = make_float4(m[4], m[5], m[6], m[7]);
        }
        float s2 = 0.f;
        #pragma unroll
        for (int j = 0; j < 8; j++) s2 = fmaf(m[j], m[j], s2);
        s2 += __shfl_xor_sync(0xffffffffu, s2, 1);
        s2 += __shfl_xor_sync(0xffffffffu, s2, 2);
        s2 += __shfl_xor_sync(0xffffffffu, s2, 4);
        if ((t & 31) == 0) g_sq[node0 + n] = s2;
    }
}

// ---------------- mean pool + output MLP -> d_out[64]
__global__ __launch_bounds__(256) void k_final(
    const float* __restrict__ w1, const float* __restrict__ b1,
    const float* __restrict__ w2, const float* __restrict__ b2,
    float* __restrict__ out)
{
    int b = blockIdx.x, t = threadIdx.x;
    const float* hb = g_h0 + (size_t)b * NM * NH;   // edgeconv2 wrote g_h0
    __shared__ float red[256];
    __shared__ float g[64];
    __shared__ float hid[32];

    int c = t & 63, r0 = t >> 6;
    float acc = 0.f;
    for (int m = r0; m < NM; m += 4) acc += hb[(size_t)m * NH + c];
    red[t] = acc;
    __syncthreads();
    if (t < 64)
        g[t] = (red[t] + red[t+64] + red[t+128] + red[t+192]) * (1.f/1024.f);
    __syncthreads();
    if (t < 32) {
        float a = b1[t];
        #pragma unroll 8
        for (int k = 0; k < 64; k++) a = fmaf(g[k], w1[k*32 + t], a);
        hid[t] = fmaxf(a, 0.f);
    }
    __syncthreads();
    if (t < 32) {
        float v = hid[t] * w2[t];
        #pragma unroll
        for (int off = 16; off > 0; off >>= 1)
            v += __shfl_down_sync(0xffffffffu, v, off);
        if (t == 0) out[b] = v + b2[0];
    }
}

// ---------------- launch ----------------------------------------------------
extern "C" void kernel_launch(void* const* d_in, const int* in_sizes, int n_in,
                              void* d_out, int out_size)
{
    const float* x      = (const float*)d_in[0];
    // d_in[1] = batch (int64) — equal-size graphs, unused
    const float* enc_w1 = (const float*)d_in[2];
    const float* enc_b1 = (const float*)d_in[3];
    const float* enc_w2 = (const float*)d_in[4];
    const float* enc_b2 = (const float*)d_in[5];
    const float* ec1_w1 = (const float*)d_in[6];
    const float* ec1_b1 = (const float*)d_in[7];
    const float* ec1_w2 = (const float*)d_in[8];
    const float* ec1_b2 = (const float*)d_in[9];
    const float* ec2_w1 = (const float*)d_in[10];
    const float* ec2_b1 = (const float*)d_in[11];
    const float* ec2_w2 = (const float*)d_in[12];
    const float* ec2_b2 = (const float*)d_in[13];
    const float* out_w1 = (const float*)d_in[14];
    const float* out_b1 = (const float*)d_in[15];
    const float* out_w2 = (const float*)d_in[16];
    const float* out_b2 = (const float*)d_in[17];
    float* out = (float*)d_out;

    cudaFuncSetAttribute(k_edgeconv, cudaFuncAttributeMaxDynamicSharedMemorySize,
                         EC_SMEM_BYTES);
    cudaFuncSetAttribute(k_knn, cudaFuncAttributeMaxDynamicSharedMemorySize,
                         KNN_SMEM_BYTES);

    k_encoder<<<NN/256, 256>>>(x, enc_w1, enc_b1, enc_w2, enc_b2);
    k_knn<<<dim3(NM/128, NB), 128, KNN_SMEM_BYTES>>>(0);
    k_edgeconv<<<EC_GRID, 256, EC_SMEM_BYTES>>>(0, ec1_w1, ec1_b1, ec1_w2, ec1_b2);
    k_knn<<<dim3(NM/128, NB), 128, KNN_SMEM_BYTES>>>(1);
    k_edgeconv<<<EC_GRID, 256, EC_SMEM_BYTES>>>(1, ec2_w1, ec2_b1, ec2_w2, ec2_b2);
    k_final<<<NB, 256>>>(out_w1, out_b1, out_w2, out_b2, out);
}